// round 2
// baseline (speedup 1.0000x reference)
#include <cuda_runtime.h>
#include <math.h>

#define MAXN 400000
#define TPB  128
#define SPT  4      // samples per thread

// Accumulators: [0..3]=S0(k)  [4..15]=S1(k*3+d)  [16..39]=S2(k*6+m)  [40]=loss1  [41]=esum
__device__ double g_acc[42];
__device__ float  g_z[3 * MAXN];          // planar: z1 | cos | euc
__device__ float  g_logphi[4], g_item3[4];
__device__ float  g_muv[4][3], g_sinv[4][6];
__device__ double g_loss3;

__device__ __forceinline__ float tanh_f(float x) {
    float y = fminf(fmaxf(x, -8.f), 8.f);
    float e = __expf(2.f * y);
    return __fdividef(e - 1.f, e + 1.f);
}

__device__ __forceinline__ float wsum(float v) {
#pragma unroll
    for (int o = 16; o; o >>= 1) v += __shfl_down_sync(0xffffffffu, v, o);
    return v;
}

__global__ void zero_kernel() {
    int t = threadIdx.x;
    if (t < 42) g_acc[t] = 0.0;
}

__global__ void __launch_bounds__(TPB) fwd_kernel(
    const float* __restrict__ x1,
    const float* __restrict__ ew1, const float* __restrict__ eb1,
    const float* __restrict__ ew2, const float* __restrict__ eb2,
    const float* __restrict__ ew3, const float* __restrict__ eb3,
    const float* __restrict__ dw1, const float* __restrict__ db1,
    const float* __restrict__ dw2, const float* __restrict__ db2,
    const float* __restrict__ dw3, const float* __restrict__ db3,
    const float* __restrict__ tw1, const float* __restrict__ tb1,
    const float* __restrict__ tw2, const float* __restrict__ tb2,
    int n)
{
    __shared__ __align__(16) float sW1[2048];
    __shared__ __align__(16) float sB1[16];
    __shared__ __align__(16) float sW2[128];
    __shared__ __align__(16) float sB2[8];
    __shared__ __align__(16) float sW3[8];
    __shared__ __align__(16) float sB3[4];
    __shared__ __align__(16) float sDW1[8];
    __shared__ __align__(16) float sDB1[8];
    __shared__ __align__(16) float sDW2[128];
    __shared__ __align__(16) float sDB2[16];
    __shared__ __align__(16) float sDW3T[2048];   // transposed: [j][i]
    __shared__ __align__(16) float sDB3[128];
    __shared__ __align__(16) float sTW1[24];
    __shared__ __align__(16) float sTB1[8];
    __shared__ __align__(16) float sTW2[32];
    __shared__ __align__(16) float sTB2[4];

    const int tid = threadIdx.x;
    for (int i = tid; i < 2048; i += TPB) sW1[i] = ew1[i];
    for (int i = tid; i < 16;   i += TPB) sB1[i] = eb1[i];
    for (int i = tid; i < 128;  i += TPB) sW2[i] = ew2[i];
    for (int i = tid; i < 8;    i += TPB) sB2[i] = eb2[i];
    if (tid < 8)  sW3[tid] = ew3[tid];
    if (tid == 0) sB3[0]   = eb3[0];
    if (tid < 8)  { sDW1[tid] = dw1[tid]; sDB1[tid] = db1[tid]; }
    for (int i = tid; i < 128;  i += TPB) sDW2[i] = dw2[i];
    for (int i = tid; i < 16;   i += TPB) sDB2[i] = db2[i];
    for (int i = tid; i < 2048; i += TPB) { int r = i >> 7, j = i & 127; sDW3T[j * 16 + r] = dw3[i]; }
    for (int i = tid; i < 128;  i += TPB) sDB3[i] = db3[i];
    if (tid < 24) sTW1[tid] = tw1[tid];
    if (tid < 8)  sTB1[tid] = tb1[tid];
    if (tid < 32) sTW2[tid] = tw2[tid];
    if (tid < 4)  sTB2[tid] = tb2[tid];
    __syncthreads();

    const int g = (blockIdx.x * TPB + tid) * SPT;

    const float4* xp[SPT];
    float validf[SPT];
#pragma unroll
    for (int s = 0; s < SPT; s++) {
        int idx = g + s;
        validf[s] = (idx < n) ? 1.f : 0.f;
        if (idx >= n) idx = 0;
        xp[s] = (const float4*)(x1 + (size_t)idx * 128);
    }

    // ---------------- encoder layer 1 (128->16) + ||x1||^2 ----------------
    float acc[SPT][16];
#pragma unroll
    for (int s = 0; s < SPT; s++)
#pragma unroll
        for (int j = 0; j < 16; j++) acc[s][j] = sB1[j];

    float n1[SPT];
#pragma unroll
    for (int s = 0; s < SPT; s++) n1[s] = 0.f;

#pragma unroll 2
    for (int c = 0; c < 32; c++) {
        float4 v[SPT];
#pragma unroll
        for (int s = 0; s < SPT; s++) v[s] = xp[s][c];
#pragma unroll
        for (int s = 0; s < SPT; s++)
            n1[s] = fmaf(v[s].x, v[s].x, fmaf(v[s].y, v[s].y,
                    fmaf(v[s].z, v[s].z, fmaf(v[s].w, v[s].w, n1[s]))));

        const float4* wr = (const float4*)&sW1[c * 64];
#pragma unroll
        for (int r = 0; r < 4; r++) {
            float4 w0 = wr[r * 4 + 0], w1 = wr[r * 4 + 1];
            float4 w2 = wr[r * 4 + 2], w3 = wr[r * 4 + 3];
#pragma unroll
            for (int s = 0; s < SPT; s++) {
                float xv = (r == 0) ? v[s].x : (r == 1) ? v[s].y : (r == 2) ? v[s].z : v[s].w;
                acc[s][0]  = fmaf(xv, w0.x, acc[s][0]);
                acc[s][1]  = fmaf(xv, w0.y, acc[s][1]);
                acc[s][2]  = fmaf(xv, w0.z, acc[s][2]);
                acc[s][3]  = fmaf(xv, w0.w, acc[s][3]);
                acc[s][4]  = fmaf(xv, w1.x, acc[s][4]);
                acc[s][5]  = fmaf(xv, w1.y, acc[s][5]);
                acc[s][6]  = fmaf(xv, w1.z, acc[s][6]);
                acc[s][7]  = fmaf(xv, w1.w, acc[s][7]);
                acc[s][8]  = fmaf(xv, w2.x, acc[s][8]);
                acc[s][9]  = fmaf(xv, w2.y, acc[s][9]);
                acc[s][10] = fmaf(xv, w2.z, acc[s][10]);
                acc[s][11] = fmaf(xv, w2.w, acc[s][11]);
                acc[s][12] = fmaf(xv, w3.x, acc[s][12]);
                acc[s][13] = fmaf(xv, w3.y, acc[s][13]);
                acc[s][14] = fmaf(xv, w3.z, acc[s][14]);
                acc[s][15] = fmaf(xv, w3.w, acc[s][15]);
            }
        }
    }

    float h1[SPT][16];
#pragma unroll
    for (int s = 0; s < SPT; s++)
#pragma unroll
        for (int j = 0; j < 16; j++) h1[s][j] = tanh_f(acc[s][j]);

    // ---------------- encoder layer 2 (16->8) ----------------
    float h2[SPT][8];
#pragma unroll
    for (int j = 0; j < 8; j++) {
        float t[SPT];
#pragma unroll
        for (int s = 0; s < SPT; s++) t[s] = sB2[j];
#pragma unroll
        for (int i = 0; i < 16; i++) {
            float w = sW2[i * 8 + j];
#pragma unroll
            for (int s = 0; s < SPT; s++) t[s] = fmaf(h1[s][i], w, t[s]);
        }
#pragma unroll
        for (int s = 0; s < SPT; s++) h2[s][j] = tanh_f(t[s]);
    }

    // ---------------- encoder layer 3 (8->1) ----------------
    float z1[SPT];
#pragma unroll
    for (int s = 0; s < SPT; s++) {
        float t = sB3[0];
#pragma unroll
        for (int i = 0; i < 8; i++) t = fmaf(h2[s][i], sW3[i], t);
        z1[s] = tanh_f(t);
    }

    // ---------------- decoder layer 1 (1->8) ----------------
    float d1[SPT][8];
#pragma unroll
    for (int j = 0; j < 8; j++) {
        float w = sDW1[j], b = sDB1[j];
#pragma unroll
        for (int s = 0; s < SPT; s++) d1[s][j] = tanh_f(fmaf(z1[s], w, b));
    }

    // ---------------- decoder layer 2 (8->16) ----------------
    float d2[SPT][16];
#pragma unroll
    for (int j = 0; j < 16; j++) {
        float t[SPT];
#pragma unroll
        for (int s = 0; s < SPT; s++) t[s] = sDB2[j];
#pragma unroll
        for (int i = 0; i < 8; i++) {
            float w = sDW2[i * 16 + j];
#pragma unroll
            for (int s = 0; s < SPT; s++) t[s] = fmaf(d1[s][i], w, t[s]);
        }
#pragma unroll
        for (int s = 0; s < SPT; s++) d2[s][j] = tanh_f(t[s]);
    }

    // ---------------- decoder layer 3 (16->128) + distances ----------------
    float dotv[SPT], n2[SPT], e2[SPT];
#pragma unroll
    for (int s = 0; s < SPT; s++) { dotv[s] = 0.f; n2[s] = 0.f; e2[s] = 0.f; }

#pragma unroll 2
    for (int c = 0; c < 32; c++) {
        float4 xv[SPT];
#pragma unroll
        for (int s = 0; s < SPT; s++) xv[s] = xp[s][c];
#pragma unroll
        for (int u = 0; u < 4; u++) {
            const int j = c * 4 + u;
            const float4* wj = (const float4*)&sDW3T[j * 16];
            float4 w0 = wj[0], w1 = wj[1], w2 = wj[2], w3 = wj[3];
            float b = sDB3[j];
#pragma unroll
            for (int s = 0; s < SPT; s++) {
                float y = b;
                y = fmaf(d2[s][0],  w0.x, y);
                y = fmaf(d2[s][1],  w0.y, y);
                y = fmaf(d2[s][2],  w0.z, y);
                y = fmaf(d2[s][3],  w0.w, y);
                y = fmaf(d2[s][4],  w1.x, y);
                y = fmaf(d2[s][5],  w1.y, y);
                y = fmaf(d2[s][6],  w1.z, y);
                y = fmaf(d2[s][7],  w1.w, y);
                y = fmaf(d2[s][8],  w2.x, y);
                y = fmaf(d2[s][9],  w2.y, y);
                y = fmaf(d2[s][10], w2.z, y);
                y = fmaf(d2[s][11], w2.w, y);
                y = fmaf(d2[s][12], w3.x, y);
                y = fmaf(d2[s][13], w3.y, y);
                y = fmaf(d2[s][14], w3.z, y);
                y = fmaf(d2[s][15], w3.w, y);
                float xs = (u == 0) ? xv[s].x : (u == 1) ? xv[s].y : (u == 2) ? xv[s].z : xv[s].w;
                dotv[s] = fmaf(xs, y, dotv[s]);
                n2[s]   = fmaf(y, y, n2[s]);
                float d = xs - y;
                e2[s]   = fmaf(d, d, e2[s]);
            }
        }
    }

    // ---------------- distances, estimator, softmax ----------------
    float gam[SPT][4], cosd[SPT], eucd[SPT];
#pragma unroll
    for (int s = 0; s < SPT; s++) {
        float prod = sqrtf(n1[s]) * sqrtf(n2[s]);
        float cd = __fdividef(dotv[s], prod);
        float ed = sqrtf(e2[s]);
        cosd[s] = cd; eucd[s] = ed;

        float eh[8];
#pragma unroll
        for (int j = 0; j < 8; j++) {
            float t = sTB1[j];
            t = fmaf(z1[s], sTW1[j],      t);
            t = fmaf(cd,    sTW1[8 + j],  t);
            t = fmaf(ed,    sTW1[16 + j], t);
            eh[j] = tanh_f(t);
        }
        float lg[4];
#pragma unroll
        for (int k = 0; k < 4; k++) {
            float t = sTB2[k];
#pragma unroll
            for (int i = 0; i < 8; i++) t = fmaf(eh[i], sTW2[i * 4 + k], t);
            lg[k] = t;
        }
        float m = fmaxf(fmaxf(lg[0], lg[1]), fmaxf(lg[2], lg[3]));
        float es[4], ssum = 0.f;
#pragma unroll
        for (int k = 0; k < 4; k++) { es[k] = __expf(lg[k] - m); ssum += es[k]; }
        float inv = __fdividef(validf[s], ssum);   // folds validity into gamma
#pragma unroll
        for (int k = 0; k < 4; k++) gam[s][k] = es[k] * inv;

        int idx = g + s;
        if (idx < n) {
            g_z[idx]            = z1[s];
            g_z[MAXN + idx]     = cd;
            g_z[2 * MAXN + idx] = ed;
        }
    }

    // ---------------- per-thread moment contributions ----------------
    float vals[41];
#pragma unroll
    for (int q = 0; q < 41; q++) vals[q] = 0.f;

#pragma unroll
    for (int s = 0; s < SPT; s++) {
        float zv0 = z1[s], zv1 = cosd[s], zv2 = eucd[s];
        float p00 = zv0 * zv0, p01 = zv0 * zv1, p02 = zv0 * zv2;
        float p11 = zv1 * zv1, p12 = zv1 * zv2, p22 = zv2 * zv2;
        vals[40] += e2[s] * validf[s];
#pragma unroll
        for (int k = 0; k < 4; k++) {
            float gk = gam[s][k];
            vals[k] += gk;
            vals[4 + k * 3 + 0]  = fmaf(gk, zv0, vals[4 + k * 3 + 0]);
            vals[4 + k * 3 + 1]  = fmaf(gk, zv1, vals[4 + k * 3 + 1]);
            vals[4 + k * 3 + 2]  = fmaf(gk, zv2, vals[4 + k * 3 + 2]);
            vals[16 + k * 6 + 0] = fmaf(gk, p00, vals[16 + k * 6 + 0]);
            vals[16 + k * 6 + 1] = fmaf(gk, p01, vals[16 + k * 6 + 1]);
            vals[16 + k * 6 + 2] = fmaf(gk, p02, vals[16 + k * 6 + 2]);
            vals[16 + k * 6 + 3] = fmaf(gk, p11, vals[16 + k * 6 + 3]);
            vals[16 + k * 6 + 4] = fmaf(gk, p12, vals[16 + k * 6 + 4]);
            vals[16 + k * 6 + 5] = fmaf(gk, p22, vals[16 + k * 6 + 5]);
        }
    }

    const int lane = tid & 31;
#pragma unroll
    for (int q = 0; q < 41; q++) {
        float r = wsum(vals[q]);
        if (lane == 0) atomicAdd(&g_acc[q], (double)r);
    }
}

__global__ void finalize_kernel(int n) {
    if (threadIdx.x == 0 && blockIdx.x == 0) {
        const double TWO_PI = 6.283185307179586;
        double loss3 = 0.0;
        for (int k = 0; k < 4; k++) {
            double gs = g_acc[k];
            double m0 = g_acc[4 + k * 3 + 0] / gs;
            double m1 = g_acc[4 + k * 3 + 1] / gs;
            double m2 = g_acc[4 + k * 3 + 2] / gs;
            double a = g_acc[16 + k * 6 + 0] / gs - m0 * m0;  // xx
            double b = g_acc[16 + k * 6 + 1] / gs - m0 * m1;  // xy
            double c = g_acc[16 + k * 6 + 2] / gs - m0 * m2;  // xz
            double d = g_acc[16 + k * 6 + 3] / gs - m1 * m1;  // yy
            double e = g_acc[16 + k * 6 + 4] / gs - m1 * m2;  // yz
            double f = g_acc[16 + k * 6 + 5] / gs - m2 * m2;  // zz

            double det = a * (d * f - e * e) - b * (b * f - c * e) + c * (b * e - c * d);
            double id = 1.0 / det;
            g_sinv[k][0] = (float)((d * f - e * e) * id);
            g_sinv[k][1] = (float)((c * e - b * f) * id);
            g_sinv[k][2] = (float)((b * e - c * d) * id);
            g_sinv[k][3] = (float)((a * f - c * c) * id);
            g_sinv[k][4] = (float)((b * c - a * e) * id);
            g_sinv[k][5] = (float)((a * d - b * b) * id);
            g_muv[k][0] = (float)m0; g_muv[k][1] = (float)m1; g_muv[k][2] = (float)m2;

            double phi = gs / (double)n;
            g_logphi[k] = (float)log(phi);
            g_item3[k]  = (float)(0.5 * log(TWO_PI * TWO_PI * TWO_PI * det));

            loss3 += 1.0 / a + 1.0 / d + 1.0 / f;
        }
        g_loss3 = 1e-4 * loss3;
    }
}

__global__ void energy_kernel(float* __restrict__ out, int n) {
    int i = blockIdx.x * blockDim.x + threadIdx.x;
    bool v = i < n;
    int ii = v ? i : 0;
    float z0 = g_z[ii], zc = g_z[MAXN + ii], ze = g_z[2 * MAXN + ii];
    float e = 0.f;
#pragma unroll
    for (int k = 0; k < 4; k++) {
        float a = z0 - g_muv[k][0];
        float b = zc - g_muv[k][1];
        float c = ze - g_muv[k][2];
        float q = g_sinv[k][0] * a * a + g_sinv[k][3] * b * b + g_sinv[k][5] * c * c
                + 2.f * (g_sinv[k][1] * a * b + g_sinv[k][2] * a * c + g_sinv[k][4] * b * c);
        e += g_item3[k] - g_logphi[k] + 0.5f * q;
    }
    if (v) out[i] = e;
    float r = wsum(v ? e : 0.f);
    if ((threadIdx.x & 31) == 0) atomicAdd(&g_acc[41], (double)r);
}

__global__ void loss_kernel(float* __restrict__ out, int n, int has_loss) {
    if (threadIdx.x == 0 && has_loss) {
        double loss = g_acc[40] / (double)n + 0.01 * (g_acc[41] / (double)n) + g_loss3;
        out[n] = (float)loss;
    }
}

extern "C" void kernel_launch(void* const* d_in, const int* in_sizes, int n_in,
                              void* d_out, int out_size) {
    const float* x1  = (const float*)d_in[0];
    const float* ew1 = (const float*)d_in[1];
    const float* eb1 = (const float*)d_in[2];
    const float* ew2 = (const float*)d_in[3];
    const float* eb2 = (const float*)d_in[4];
    const float* ew3 = (const float*)d_in[5];
    const float* eb3 = (const float*)d_in[6];
    const float* dw1 = (const float*)d_in[7];
    const float* db1 = (const float*)d_in[8];
    const float* dw2 = (const float*)d_in[9];
    const float* db2 = (const float*)d_in[10];
    const float* dw3 = (const float*)d_in[11];
    const float* db3 = (const float*)d_in[12];
    const float* tw1 = (const float*)d_in[13];
    const float* tb1 = (const float*)d_in[14];
    const float* tw2 = (const float*)d_in[15];
    const float* tb2 = (const float*)d_in[16];

    int n = in_sizes[0] / 128;
    if (n > MAXN) n = MAXN;
    float* out = (float*)d_out;

    zero_kernel<<<1, 64>>>();
    int blocks = (n + TPB * SPT - 1) / (TPB * SPT);
    fwd_kernel<<<blocks, TPB>>>(x1, ew1, eb1, ew2, eb2, ew3, eb3,
                                dw1, db1, dw2, db2, dw3, db3,
                                tw1, tb1, tw2, tb2, n);
    finalize_kernel<<<1, 32>>>(n);
    energy_kernel<<<(n + 255) / 256, 256>>>(out, n);
    loss_kernel<<<1, 32>>>(out, n, out_size > n ? 1 : 0);
}